// round 16
// baseline (speedup 1.0000x reference)
#include <cuda_runtime.h>
#include <cuda_fp16.h>

#define NBINS 28
#define HID   16
#define FEAT  8
#define TPB   128   // threads per block
#define EPT   3     // elements per thread (weight-load amortization)

typedef unsigned long long u64;

// mhless table: t[dl] = exp(ml_mlp(dl) - 0.25*dl) for dl = 1..40
__device__ float g_mhless[41];

__device__ __forceinline__ float sigmoid_exact(float v) {
    return 1.0f / (1.0f + __expf(-v));
}
__device__ __forceinline__ u64 pack2(float lo, float hi) {
    u64 r; asm("mov.b64 %0, {%1, %2};" : "=l"(r) : "f"(lo), "f"(hi)); return r;
}
__device__ __forceinline__ void unpack2(u64 v, float& lo, float& hi) {
    asm("mov.b64 {%0, %1}, %2;" : "=f"(lo), "=f"(hi) : "l"(v));
}
__device__ __forceinline__ u64 fma2(u64 a, u64 b, u64 c) {
    u64 d; asm("fma.rn.f32x2 %0, %1, %2, %3;" : "=l"(d) : "l"(a), "l"(b), "l"(c)); return d;
}
__device__ __forceinline__ float tanh_fast(float x) {
    float y; asm("tanh.approx.f32 %0, %1;" : "=f"(y) : "f"(x)); return y;
}

// ---------------------------------------------------------------------------
// Init kernel (separate launch — R13 proved per-block table fusion is poison):
// exact ml-MLP table for dl = 1..40; writes dl2_scores baseline into out_bins.
// ---------------------------------------------------------------------------
__global__ void dnn_init_kernel(
    const float* __restrict__ ml_W1, const float* __restrict__ ml_b1,
    const float* __restrict__ ml_W2, const float* __restrict__ ml_b2,
    const float* __restrict__ ml_W3, const float* __restrict__ ml_b3,
    float* __restrict__ out_bins)
{
    int t = threadIdx.x;
    if (t >= 40) return;
    float dl = (float)(t + 1);

    float h1[HID];
    #pragma unroll
    for (int o = 0; o < HID; o++)
        h1[o] = sigmoid_exact(fmaf(dl, ml_W1[o], ml_b1[o]));

    float h2[HID];
    #pragma unroll
    for (int o = 0; o < HID; o++) {
        float a = ml_b2[o];
        #pragma unroll
        for (int i = 0; i < HID; i++)
            a = fmaf(h1[i], ml_W2[i * HID + o], a);
        h2[o] = sigmoid_exact(a);
    }

    float phi = ml_b3[0];
    #pragma unroll
    for (int i = 0; i < HID; i++)
        phi = fmaf(h2[i], ml_W3[i], phi);

    float v = __expf(phi - 0.25f * dl);
    g_mhless[t + 1] = v;
    if (t < NBINS) out_bins[t] = v;
}

// ---------------------------------------------------------------------------
// Main kernel. Tanh-folded MLP, packed fma.rn.f32x2, EPT=3, hoisted LDGs,
// two-output-half layers. Register diet: features kept packed (u64),
// t1 stored as fp16 half2, del/mh packed -> ~82 regs -> 6 blocks/SM.
// ---------------------------------------------------------------------------
__global__ __launch_bounds__(TPB, 6)
void dnn_main_kernel(
    const float* __restrict__ x_feat,
    const float* __restrict__ W1, const float* __restrict__ b1,
    const float* __restrict__ W2, const float* __restrict__ b2,
    const float* __restrict__ W3, const float* __restrict__ b3,
    const int*   __restrict__ del_lens,
    const int*   __restrict__ mh_len,
    float* __restrict__ out,
    float* __restrict__ out_bins,
    int n)
{
    __shared__ __align__(16) float sA1[FEAT * HID];   // W1 * 0.5
    __shared__ __align__(16) float sC1[HID];          // b1 * 0.5
    __shared__ __align__(16) float sA2[HID * HID];    // W2 * 0.25
    __shared__ __align__(16) float sC2[HID];          // b2*0.5 + colsum(W2)*0.25
    __shared__ __align__(16) float sA3[HID];          // W3 * 0.5
    __shared__ float sC3;                             // b3 + sum(W3)*0.5
    __shared__ float stab[41];
    __shared__ float sbins[NBINS];

    const int tid = threadIdx.x;

    // ---- per-element global loads FIRST (latency hidden behind staging) ----
    int  gi[EPT];
    bool vv[EPT];
    #pragma unroll
    for (int e = 0; e < EPT; e++) {
        gi[e] = blockIdx.x * (TPB * EPT) + e * TPB + tid;
        vv[e] = (gi[e] < n);
    }
    u64 xp[EPT][4];          // packed feature pairs (f0,f1)(f2,f3)(f4,f5)(f6,f7)
    int dm[EPT];             // del | (mh << 16)
    #pragma unroll
    for (int e = 0; e < EPT; e++) {
        int j = vv[e] ? gi[e] : 0;
        const ulonglong2* px = reinterpret_cast<const ulonglong2*>(x_feat + (size_t)j * FEAT);
        ulonglong2 q0 = px[0], q1 = px[1];
        xp[e][0] = q0.x; xp[e][1] = q0.y; xp[e][2] = q1.x; xp[e][3] = q1.y;
        dm[e] = del_lens[j] | (mh_len[j] << 16);
    }

    // ---- weight staging ----
    for (int i = tid; i < FEAT * HID; i += TPB) sA1[i] = 0.5f * W1[i];
    for (int i = tid; i < HID * HID; i += TPB) sA2[i] = 0.25f * W2[i];
    if (tid < HID) {
        sC1[tid] = 0.5f * b1[tid];
        float s = 0.0f;
        #pragma unroll
        for (int i = 0; i < HID; i++) s += W2[i * HID + tid];
        sC2[tid] = fmaf(0.25f, s, 0.5f * b2[tid]);
        sA3[tid] = 0.5f * W3[tid];
    }
    if (tid == 32) {
        float s = 0.0f;
        #pragma unroll
        for (int i = 0; i < HID; i++) s += W3[i];
        sC3 = fmaf(0.5f, s, b3[0]);
    }
    if (tid >= 64 && tid < 64 + 41) stab[tid - 64] = g_mhless[tid - 64];
    if (tid >= 96 && tid < 96 + NBINS) sbins[tid - 96] = 0.0f;
    __syncthreads();

    // ---- layer 1 in two output-halves; t1 stored as fp16 half2 ----
    __half2 t1h[EPT][8];     // t1h[e][j] = (t1[2j], t1[2j+1])
    #pragma unroll
    for (int h = 0; h < 2; h++) {
        u64 z[EPT][4];
        {
            const ulonglong2* cp = reinterpret_cast<const ulonglong2*>(sC1 + h * 8);
            ulonglong2 c0 = cp[0], c1v = cp[1];
            #pragma unroll
            for (int e = 0; e < EPT; e++) {
                z[e][0]=c0.x; z[e][1]=c0.y; z[e][2]=c1v.x; z[e][3]=c1v.y;
            }
        }
        #pragma unroll
        for (int jp = 0; jp < 4; jp++) {   // feature pairs (2jp, 2jp+1)
            const ulonglong2* w0 = reinterpret_cast<const ulonglong2*>(sA1 + (2*jp)   * HID + h * 8);
            const ulonglong2* w1 = reinterpret_cast<const ulonglong2*>(sA1 + (2*jp+1) * HID + h * 8);
            ulonglong2 wa = w0[0], wb = w0[1];
            ulonglong2 wc = w1[0], wd = w1[1];
            #pragma unroll
            for (int e = 0; e < EPT; e++) {
                float f0, f1; unpack2(xp[e][jp], f0, f1);
                u64 p0 = pack2(f0, f0);
                u64 p1 = pack2(f1, f1);
                z[e][0]=fma2(p0,wa.x,z[e][0]); z[e][1]=fma2(p0,wa.y,z[e][1]);
                z[e][2]=fma2(p0,wb.x,z[e][2]); z[e][3]=fma2(p0,wb.y,z[e][3]);
                z[e][0]=fma2(p1,wc.x,z[e][0]); z[e][1]=fma2(p1,wc.y,z[e][1]);
                z[e][2]=fma2(p1,wd.x,z[e][2]); z[e][3]=fma2(p1,wd.y,z[e][3]);
            }
        }
        #pragma unroll
        for (int e = 0; e < EPT; e++)
            #pragma unroll
            for (int o = 0; o < 4; o++) {
                float lo, hi; unpack2(z[e][o], lo, hi);
                t1h[e][h*4 + o] = __floats2half2_rn(tanh_fast(lo), tanh_fast(hi));
            }
    }

    // ---- layer 2 + layer 3, two output-halves ----
    float phi[EPT];
    #pragma unroll
    for (int e = 0; e < EPT; e++) phi[e] = sC3;

    #pragma unroll
    for (int h = 0; h < 2; h++) {
        u64 z[EPT][4];
        {
            const ulonglong2* cp = reinterpret_cast<const ulonglong2*>(sC2 + h * 8);
            ulonglong2 c0 = cp[0], c1v = cp[1];
            #pragma unroll
            for (int e = 0; e < EPT; e++) {
                z[e][0]=c0.x; z[e][1]=c0.y; z[e][2]=c1v.x; z[e][3]=c1v.y;
            }
        }
        #pragma unroll
        for (int i = 0; i < HID; i++) {
            const ulonglong2* w = reinterpret_cast<const ulonglong2*>(sA2 + i * HID + h * 8);
            ulonglong2 wa = w[0], wb = w[1];
            #pragma unroll
            for (int e = 0; e < EPT; e++) {
                __half2 hv = t1h[e][i >> 1];
                float f = __half2float((i & 1) ? __high2half(hv) : __low2half(hv));
                u64 p = pack2(f, f);
                z[e][0]=fma2(p,wa.x,z[e][0]); z[e][1]=fma2(p,wa.y,z[e][1]);
                z[e][2]=fma2(p,wb.x,z[e][2]); z[e][3]=fma2(p,wb.y,z[e][3]);
            }
        }
        #pragma unroll
        for (int o = 0; o < 4; o++) {
            float w0 = sA3[h*8 + 2*o], w1 = sA3[h*8 + 2*o + 1];
            #pragma unroll
            for (int e = 0; e < EPT; e++) {
                float lo, hi; unpack2(z[e][o], lo, hi);
                phi[e] = fmaf(tanh_fast(lo), w0, phi[e]);
                phi[e] = fmaf(tanh_fast(hi), w1, phi[e]);
            }
        }
    }

    // ---- epilogue (d/mh packed in regs) ----
    #pragma unroll
    for (int e = 0; e < EPT; e++) {
        if (vv[e]) {
            int d  = dm[e] & 0xFFFF;
            int mh = dm[e] >> 16;
            float score = __expf(fmaf(-0.25f, (float)d, phi[e]));
            float contrib = 0.0f;
            if (d == mh && d <= 40) contrib = stab[d];
            out[gi[e]] = score + contrib;
            if (d <= NBINS) atomicAdd(&sbins[d - 1], score);
        }
    }

    __syncthreads();
    if (tid < NBINS) {
        float v = sbins[tid];
        if (v != 0.0f) atomicAdd(&out_bins[tid], v);
    }
}

// ---------------------------------------------------------------------------
// Launch
// ---------------------------------------------------------------------------
extern "C" void kernel_launch(void* const* d_in, const int* in_sizes, int n_in,
                              void* d_out, int out_size)
{
    const float* x_feat = (const float*)d_in[0];
    const float* mh_W1  = (const float*)d_in[1];
    const float* mh_b1  = (const float*)d_in[2];
    const float* mh_W2  = (const float*)d_in[3];
    const float* mh_b2  = (const float*)d_in[4];
    const float* mh_W3  = (const float*)d_in[5];
    const float* mh_b3  = (const float*)d_in[6];
    const float* ml_W1  = (const float*)d_in[7];
    const float* ml_b1  = (const float*)d_in[8];
    const float* ml_W2  = (const float*)d_in[9];
    const float* ml_b2  = (const float*)d_in[10];
    const float* ml_W3  = (const float*)d_in[11];
    const float* ml_b3  = (const float*)d_in[12];
    const int*   del_lens = (const int*)d_in[13];
    const int*   mh_len   = (const int*)d_in[14];

    int n = in_sizes[13];
    float* out      = (float*)d_out;
    float* out_bins = out + n;

    dnn_init_kernel<<<1, 64>>>(ml_W1, ml_b1, ml_W2, ml_b2, ml_W3, ml_b3, out_bins);

    int blocks = (n + TPB * EPT - 1) / (TPB * EPT);
    dnn_main_kernel<<<blocks, TPB>>>(x_feat,
                                     mh_W1, mh_b1, mh_W2, mh_b2, mh_W3, mh_b3,
                                     del_lens, mh_len,
                                     out, out_bins, n);
}